// round 3
// baseline (speedup 1.0000x reference)
#include <cuda_runtime.h>
#include <cstdint>

// ---------------- problem constants ----------------
#define NROWS   16384      // 64*256*256 / 256
#define DDIM    256
#define KCODES  8192
#define DECAY   0.99f
#define ONE_M_DECAY 0.01f
#define EPSV    1e-5f

// output layout (concatenated, float32, tuple order)
#define OFF_Q     0L
#define OFF_LOSS  4194304L
#define OFF_IDX   4194305L
#define OFF_CS    4210689L
#define OFF_EMAW  4218881L
#define OFF_EMB   6316033L

// ---------------- scratch (device globals; no allocs allowed) ----------------
__device__ float g_emb [KCODES * DDIM];     // affine codebook, row-major [K][D]
__device__ float g_embP[DDIM * KCODES];     // pair-interleaved: [d/2][k][2]
__device__ float g_embsq[KCODES];
__device__ int   g_idx [NROWS];
__device__ float g_counts[KCODES];
__device__ float g_dw  [KCODES * DDIM];
__device__ float g_loss;
__device__ float g_nsum;

// ---------------- kernel 0: zero scratch ----------------
__global__ void zero_kernel() {
    long total = (long)KCODES * DDIM + KCODES + 2;
    for (long i = (long)blockIdx.x * blockDim.x + threadIdx.x; i < total;
         i += (long)gridDim.x * blockDim.x) {
        if (i < (long)KCODES * DDIM)               g_dw[i] = 0.f;
        else if (i < (long)KCODES * DDIM + KCODES) g_counts[i - (long)KCODES * DDIM] = 0.f;
        else if (i == (long)KCODES * DDIM + KCODES) g_loss = 0.f;
        else                                        g_nsum = 0.f;
    }
}

// ---------------- kernel 1: affine transform + pair-interleave + norms ----------------
// grid = KCODES blocks, 256 threads (one per d)
__global__ void prep_kernel(const float* __restrict__ embedding,
                            const float* __restrict__ amean,
                            const float* __restrict__ astd) {
    int k = blockIdx.x;
    int d = threadIdx.x;
    float v = amean[d] + astd[d] * embedding[(long)k * DDIM + d];
    g_emb[(long)k * DDIM + d] = v;
    // paired layout: row d2 = d>>1 holds (even,odd) for every code, contiguous over k
    g_embP[(long)(d >> 1) * (2 * KCODES) + k * 2 + (d & 1)] = v;

    float s = v * v;
    #pragma unroll
    for (int off = 16; off; off >>= 1)
        s += __shfl_down_sync(0xffffffffu, s, off);
    __shared__ float ws[8];
    if ((d & 31) == 0) ws[d >> 5] = s;
    __syncthreads();
    if (d == 0) {
        float t = 0.f;
        #pragma unroll
        for (int i = 0; i < 8; i++) t += ws[i];
        g_embsq[k] = t;
    }
}

// ---------------- kernel 2: fused distance GEMM + argmin (packed f32x2) ----------------
// BM=64 rows, BN=128 codes per chunk, 256 threads.
// microtile: TM=8 rows x TN=4 cols; K-dim packed 2-wide into f32x2.
#define BM   64
#define BN   128
#define TM   8
#define TN   4
#define D2   (DDIM / 2)      // 128 packed-K rows
#define BK2  16              // packed-K rows staged per e_s refill
#define S2   66              // x_s2 row stride in float2 (64 + 2 pad)

__device__ __forceinline__ void ffma2(unsigned long long& d,
                                      unsigned long long a,
                                      unsigned long long b) {
    asm("fma.rn.f32x2 %0, %1, %2, %0;" : "+l"(d) : "l"(a), "l"(b));
}

__global__ void __launch_bounds__(256, 2)
argmin_kernel(const float* __restrict__ x) {
    extern __shared__ float smem[];
    float2* x_s2 = reinterpret_cast<float2*>(smem);              // [D2][S2]
    unsigned long long* e_s =
        reinterpret_cast<unsigned long long*>(smem + D2 * S2 * 2); // [BK2][BN] pairs

    const int tid = threadIdx.x;
    const int ty  = tid >> 5;          // 0..7 row group
    const int tx  = tid & 31;          // lane -> column owner (stride-32 cols)
    const int rowBase = blockIdx.x * BM;
    const int trow = ty * TM;

    // load x tile: x_s2[d2][r] = (x[r][2*d2], x[r][2*d2+1])
    for (int i = tid; i < BM * DDIM; i += 256) {
        int r = i >> 8;
        int d = i & 255;
        smem[(d >> 1) * (S2 * 2) + r * 2 + (d & 1)] =
            x[(long)(rowBase + r) * DDIM + d];
    }

    float minv[TM];
    int   mini[TM];
    #pragma unroll
    for (int i = 0; i < TM; i++) { minv[i] = 3.4e38f; mini[i] = 0; }

    // staging ids: 16 groups of 16 lanes; each copies 4 float4 (one d2-row is 256 floats)
    const int er  = tid >> 4;          // 0..15 d2-row within stage
    const int el  = (tid & 15) * 16;   // float offset within row (16 floats per lane)

    for (int chunk = 0; chunk < KCODES / BN; chunk++) {
        unsigned long long acc[TM][TN];
        #pragma unroll
        for (int i = 0; i < TM; i++)
            #pragma unroll
            for (int j = 0; j < TN; j++) acc[i][j] = 0ULL;

        for (int st = 0; st < D2 / BK2; st++) {
            __syncthreads();
            // stage e_s[BK2][BN] pairs from g_embP (contiguous 256 floats per d2-row)
            {
                const float4* src = reinterpret_cast<const float4*>(
                    &g_embP[(long)(st * BK2 + er) * (2 * KCODES) + chunk * (2 * BN) + el]);
                float4* dst = reinterpret_cast<float4*>(
                    reinterpret_cast<float*>(e_s) + er * (2 * BN) + el);
                float4 v0 = src[0], v1 = src[1], v2 = src[2], v3 = src[3];
                dst[0] = v0; dst[1] = v1; dst[2] = v2; dst[3] = v3;
            }
            __syncthreads();

            #pragma unroll
            for (int k2 = 0; k2 < BK2; k2++) {
                // A: 8 consecutive row-pairs (broadcast across lanes of a warp)
                const ulonglong2* ap = reinterpret_cast<const ulonglong2*>(
                    &x_s2[(st * BK2 + k2) * S2 + trow]);
                ulonglong2 a01 = ap[0], a23 = ap[1], a45 = ap[2], a67 = ap[3];
                unsigned long long a[TM] = { a01.x, a01.y, a23.x, a23.y,
                                             a45.x, a45.y, a67.x, a67.y };
                // B: 4 cols owned by this lane (stride 32) — conflict-free LDS.64
                unsigned long long b[TN];
                #pragma unroll
                for (int j = 0; j < TN; j++)
                    b[j] = e_s[k2 * BN + tx + 32 * j];

                #pragma unroll
                for (int i = 0; i < TM; i++)
                    #pragma unroll
                    for (int j = 0; j < TN; j++)
                        ffma2(acc[i][j], a[i], b[j]);
            }
        }

        // epilogue: s = ||e||^2 - 2*(lo+hi); running min, first index wins
        #pragma unroll
        for (int j = 0; j < TN; j++) {
            int col = chunk * BN + tx + 32 * j;
            float sq = g_embsq[col];
            #pragma unroll
            for (int i = 0; i < TM; i++) {
                float lo = __uint_as_float((unsigned)(acc[i][j] & 0xffffffffULL));
                float hi = __uint_as_float((unsigned)(acc[i][j] >> 32));
                float s = fmaf(-2.f, lo + hi, sq);
                if (s < minv[i]) { minv[i] = s; mini[i] = col; }
            }
        }
    }

    // warp reduction across 32 lanes per row; ties -> smaller index
    #pragma unroll
    for (int i = 0; i < TM; i++) {
        float v = minv[i];
        int   idx = mini[i];
        #pragma unroll
        for (int off = 16; off; off >>= 1) {
            float ov = __shfl_down_sync(0xffffffffu, v, off);
            int   oi = __shfl_down_sync(0xffffffffu, idx, off);
            if (ov < v || (ov == v && oi < idx)) { v = ov; idx = oi; }
        }
        if (tx == 0) g_idx[rowBase + trow + i] = idx;
    }
}

// ---------------- kernel 3: gather quantized, loss, scatter EMA stats ----------------
__global__ void gather_kernel(const float* __restrict__ x, float* __restrict__ out) {
    int row = blockIdx.x;
    int d = threadIdx.x;
    int idx = g_idx[row];
    float xv = x[(long)row * DDIM + d];
    float qv = g_emb[(long)idx * DDIM + d];
    out[OFF_Q + (long)row * DDIM + d] = qv;

    float diff = qv - xv;
    float s = diff * diff;
    #pragma unroll
    for (int off = 16; off; off >>= 1)
        s += __shfl_down_sync(0xffffffffu, s, off);
    __shared__ float ws[8];
    if ((d & 31) == 0) ws[d >> 5] = s;
    __syncthreads();
    if (d == 0) {
        float t = 0.f;
        #pragma unroll
        for (int i = 0; i < 8; i++) t += ws[i];
        atomicAdd(&g_loss, t);
        atomicAdd(&g_counts[idx], 1.0f);
        out[OFF_IDX + row] = (float)idx;
    }
    atomicAdd(&g_dw[(long)idx * DDIM + d], xv);
}

// ---------------- kernel 4a: new_cluster_size + sum n ----------------
__global__ void cs_kernel(const float* __restrict__ cluster_size, float* __restrict__ out) {
    int k = blockIdx.x * 256 + threadIdx.x;
    float ncs = cluster_size[k] * DECAY + ONE_M_DECAY * g_counts[k];
    out[OFF_CS + k] = ncs;
    float s = ncs;
    #pragma unroll
    for (int off = 16; off; off >>= 1)
        s += __shfl_down_sync(0xffffffffu, s, off);
    __shared__ float ws[8];
    if ((threadIdx.x & 31) == 0) ws[threadIdx.x >> 5] = s;
    __syncthreads();
    if (threadIdx.x == 0) {
        float t = 0.f;
        #pragma unroll
        for (int i = 0; i < 8; i++) t += ws[i];
        atomicAdd(&g_nsum, t);
    }
}

// ---------------- kernel 4b: new_ema_w ----------------
__global__ void emaw_kernel(const float* __restrict__ ema_w, float* __restrict__ out) {
    long i = (long)blockIdx.x * blockDim.x + threadIdx.x;
    if (i < (long)KCODES * DDIM)
        out[OFF_EMAW + i] = ema_w[i] * DECAY + ONE_M_DECAY * g_dw[i];
}

// ---------------- kernel 5: smoothed normalize + loss write ----------------
__global__ void final_kernel(float* __restrict__ out) {
    int k = blockIdx.x;
    int d = threadIdx.x;
    float n = g_nsum;
    float ncs = out[OFF_CS + k];
    float smoothed = (ncs + EPSV) / (n + (float)KCODES * EPSV) * n;
    out[OFF_EMB + (long)k * DDIM + d] = out[OFF_EMAW + (long)k * DDIM + d] / smoothed;
    if (k == 0 && d == 0)
        out[OFF_LOSS] = 2.0f * g_loss / (float)((long)NROWS * DDIM);
}

// ---------------- launch ----------------
extern "C" void kernel_launch(void* const* d_in, const int* in_sizes, int n_in,
                              void* d_out, int out_size) {
    const float* x         = (const float*)d_in[0];
    const float* embedding = (const float*)d_in[1];
    const float* amean     = (const float*)d_in[2];
    const float* astd      = (const float*)d_in[3];
    const float* cs        = (const float*)d_in[4];
    const float* ema_w     = (const float*)d_in[5];
    float* out = (float*)d_out;

    (void)in_sizes; (void)n_in; (void)out_size;

    size_t smem = (D2 * S2 * 2 + BK2 * BN * 2) * sizeof(float);  // ~84 KB
    cudaFuncSetAttribute(argmin_kernel, cudaFuncAttributeMaxDynamicSharedMemorySize,
                         (int)smem);

    zero_kernel<<<2048, 256>>>();
    prep_kernel<<<KCODES, 256>>>(embedding, amean, astd);
    argmin_kernel<<<NROWS / BM, 256, smem>>>(x);
    gather_kernel<<<NROWS, 256>>>(x, out);
    cs_kernel<<<KCODES / 256, 256>>>(cs, out);
    emaw_kernel<<<(KCODES * DDIM + 255) / 256, 256>>>(ema_w, out);
    final_kernel<<<KCODES, 256>>>(out);
}

// round 7
// speedup vs baseline: 1.7399x; 1.7399x over previous
#include <cuda_runtime.h>
#include <cstdint>

// ---------------- problem constants ----------------
#define NROWS   16384
#define DDIM    256
#define KCODES  8192
#define DECAY   0.99f
#define ONE_M_DECAY 0.01f
#define EPSV    1e-5f

// output layout (concatenated, float32, tuple order)
#define OFF_Q     0L
#define OFF_LOSS  4194304L
#define OFF_IDX   4194305L
#define OFF_CS    4210689L
#define OFF_EMAW  4218881L
#define OFF_EMB   6316033L

// ---------------- scratch ----------------
__device__ float g_emb [KCODES * DDIM];
__device__ float g_ehi [KCODES * DDIM];
__device__ float g_elo [KCODES * DDIM];
__device__ float g_xhi [NROWS * DDIM];
__device__ float g_xlo [NROWS * DDIM];
__device__ float g_embsq[KCODES];
__device__ int   g_idx [NROWS];
__device__ float g_counts[KCODES];
__device__ float g_dw  [KCODES * DDIM];
__device__ float g_loss;
__device__ float g_nsum;

// ---------------- helpers ----------------
__device__ __forceinline__ float tf32_rnd(float v) {
    uint32_t u;
    asm("cvt.rna.tf32.f32 %0, %1;" : "=r"(u) : "f"(v));
    return __uint_as_float(u);
}
__device__ __forceinline__ void cpa16(uint32_t dst, const float* src) {
    asm volatile("cp.async.cg.shared.global [%0], [%1], 16;" :: "r"(dst), "l"(src));
}
__device__ __forceinline__ void cpa_commit() { asm volatile("cp.async.commit_group;"); }
__device__ __forceinline__ void cpa_wait1()  { asm volatile("cp.async.wait_group 1;" ::: "memory"); }
__device__ __forceinline__ void cpa_wait0()  { asm volatile("cp.async.wait_group 0;" ::: "memory"); }
__device__ __forceinline__ uint32_t smem_u32(const void* p) {
    uint32_t a;
    asm("{ .reg .u64 t; cvta.to.shared.u64 t, %1; cvt.u32.u64 %0, t; }" : "=r"(a) : "l"(p));
    return a;
}
__device__ __forceinline__ void mma16n8k8(float c[4],
                                          uint32_t a0, uint32_t a1, uint32_t a2, uint32_t a3,
                                          uint32_t b0, uint32_t b1) {
    asm volatile(
        "mma.sync.aligned.m16n8k8.row.col.f32.tf32.tf32.f32 "
        "{%0,%1,%2,%3}, {%4,%5,%6,%7}, {%8,%9}, {%0,%1,%2,%3};"
        : "+f"(c[0]), "+f"(c[1]), "+f"(c[2]), "+f"(c[3])
        : "r"(a0), "r"(a1), "r"(a2), "r"(a3), "r"(b0), "r"(b1));
}

// ---------------- kernel 0: zero scratch ----------------
__global__ void zero_kernel() {
    long total = (long)KCODES * DDIM + KCODES + 2;
    for (long i = (long)blockIdx.x * blockDim.x + threadIdx.x; i < total;
         i += (long)gridDim.x * blockDim.x) {
        if (i < (long)KCODES * DDIM)               g_dw[i] = 0.f;
        else if (i < (long)KCODES * DDIM + KCODES) g_counts[i - (long)KCODES * DDIM] = 0.f;
        else if (i == (long)KCODES * DDIM + KCODES) g_loss = 0.f;
        else                                        g_nsum = 0.f;
    }
}

// ---------------- kernel 1a: split x into tf32 hi/lo ----------------
__global__ void xsplit_kernel(const float* __restrict__ x) {
    long i = (long)blockIdx.x * 256 + threadIdx.x;
    float v = x[i];
    float h = tf32_rnd(v);
    g_xhi[i] = h;
    g_xlo[i] = tf32_rnd(v - h);
}

// ---------------- kernel 1b: affine codebook + split + norms ----------------
__global__ void prep_kernel(const float* __restrict__ embedding,
                            const float* __restrict__ amean,
                            const float* __restrict__ astd) {
    int k = blockIdx.x;
    int d = threadIdx.x;
    long i = (long)k * DDIM + d;
    float v = amean[d] + astd[d] * embedding[i];
    g_emb[i] = v;
    float h = tf32_rnd(v);
    g_ehi[i] = h;
    g_elo[i] = tf32_rnd(v - h);

    float s = v * v;
    #pragma unroll
    for (int off = 16; off; off >>= 1) s += __shfl_down_sync(0xffffffffu, s, off);
    __shared__ float ws[8];
    if ((d & 31) == 0) ws[d >> 5] = s;
    __syncthreads();
    if (d == 0) {
        float t = 0.f;
        #pragma unroll
        for (int i2 = 0; i2 < 8; i2++) t += ws[i2];
        g_embsq[k] = t;
    }
}

// ---------------- kernel 2: mma.sync tf32 distance GEMM + argmin ----------------
// 128 CTAs x 256 threads (8 warps). CTA: M=128 rows; 32 chunks of N=256 codes;
// K in 8 slabs of 32, cp.async double-buffered. Warp tile 64x64 (grid 2m x 4n).
#define NCHUNK   256
#define NSLABS   8
#define NCHUNKS  (KCODES / NCHUNK)    // 32
#define GTOT     (NCHUNKS * NSLABS)   // 256
#define RS       36                   // smem row stride in floats (conflict-free)
#define A_F      (128 * RS)           // 4608 floats per A split
#define B_F      (NCHUNK * RS)        // 9216 floats per B split
#define BUF_F    (2 * A_F + 2 * B_F)  // 27648 floats = 110592 B
#define FOFF_AHI 0
#define FOFF_ALO A_F
#define FOFF_BHI (2 * A_F)
#define FOFF_BLO (2 * A_F + B_F)

__global__ void __launch_bounds__(256, 1)
argmin_kernel() {
    extern __shared__ float dsm[];
    __shared__ float s_minv[128][4];
    __shared__ int   s_mini[128][4];

    const int tid   = threadIdx.x;
    const int wid   = tid >> 5;
    const int lane  = tid & 31;
    const int qrow  = lane >> 2;     // 0..7
    const int qcol  = lane & 3;      // 0..3
    const int warpM = wid & 1;       // 2 row-groups of warps
    const int warpN = wid >> 1;      // 4 col-groups
    const int rowBase = blockIdx.x * 128;

    const uint32_t dynb = smem_u32(dsm);

    // stage slab g into buffer g&1
    auto stage = [&](int g) {
        const uint32_t base = dynb + (uint32_t)(g & 1) * (BUF_F * 4);
        const int ks = g & 7, ch = g >> 3;
        const float* xh = g_xhi + (long)rowBase * DDIM + ks * 32;
        const float* xl = g_xlo + (long)rowBase * DDIM + ks * 32;
        const float* eh = g_ehi + (long)ch * NCHUNK * DDIM + ks * 32;
        const float* el = g_elo + (long)ch * NCHUNK * DDIM + ks * 32;
        #pragma unroll
        for (int i = tid; i < 1024; i += 256) {       // A: 128 rows x 8 seg
            int r = i >> 3, sg = i & 7;
            uint32_t o = (uint32_t)(r * RS + sg * 4) * 4;
            cpa16(base + FOFF_AHI * 4 + o, xh + (long)r * DDIM + sg * 4);
            cpa16(base + FOFF_ALO * 4 + o, xl + (long)r * DDIM + sg * 4);
        }
        #pragma unroll
        for (int i = tid; i < 2048; i += 256) {       // B: 256 rows x 8 seg
            int r = i >> 3, sg = i & 7;
            uint32_t o = (uint32_t)(r * RS + sg * 4) * 4;
            cpa16(base + FOFF_BHI * 4 + o, eh + (long)r * DDIM + sg * 4);
            cpa16(base + FOFF_BLO * 4 + o, el + (long)r * DDIM + sg * 4);
        }
    };

    stage(0);
    cpa_commit();

    float acc[4][8][4];     // [mt][nt][frag]
    #pragma unroll
    for (int mt = 0; mt < 4; mt++)
        #pragma unroll
        for (int nt = 0; nt < 8; nt++)
            #pragma unroll
            for (int f = 0; f < 4; f++) acc[mt][nt][f] = 0.f;

    float minv[8];
    int   mini[8];
    #pragma unroll
    for (int s = 0; s < 8; s++) { minv[s] = 3.4e38f; mini[s] = 0; }

    for (int g = 0; g < GTOT; g++) {
        if (g + 1 < GTOT) { stage(g + 1); cpa_commit(); cpa_wait1(); }
        else              { cpa_wait0(); }
        __syncthreads();

        const float* buf = dsm + (g & 1) * BUF_F;
        const uint32_t* Ah = (const uint32_t*)(buf + FOFF_AHI);
        const uint32_t* Al = (const uint32_t*)(buf + FOFF_ALO);
        const uint32_t* Bh = (const uint32_t*)(buf + FOFF_BHI);
        const uint32_t* Bl = (const uint32_t*)(buf + FOFF_BLO);

        #pragma unroll
        for (int k8 = 0; k8 < 4; k8++) {
            const int kk = k8 * 8;
            uint32_t ah[4][4], al[4][4], bh[8][2];
            #pragma unroll
            for (int mt = 0; mt < 4; mt++) {
                int ra = (warpM * 64 + mt * 16 + qrow) * RS + kk + qcol;
                ah[mt][0] = Ah[ra];            ah[mt][1] = Ah[ra + 8 * RS];
                ah[mt][2] = Ah[ra + 4];        ah[mt][3] = Ah[ra + 8 * RS + 4];
                al[mt][0] = Al[ra];            al[mt][1] = Al[ra + 8 * RS];
                al[mt][2] = Al[ra + 4];        al[mt][3] = Al[ra + 8 * RS + 4];
            }
            #pragma unroll
            for (int nt = 0; nt < 8; nt++) {
                int rb = (warpN * 64 + nt * 8 + qrow) * RS + kk + qcol;
                bh[nt][0] = Bh[rb];
                bh[nt][1] = Bh[rb + 4];
            }
            // split 0: hi x hi
            #pragma unroll
            for (int nt = 0; nt < 8; nt++)
                #pragma unroll
                for (int mt = 0; mt < 4; mt++)
                    mma16n8k8(acc[mt][nt], ah[mt][0], ah[mt][1], ah[mt][2], ah[mt][3],
                              bh[nt][0], bh[nt][1]);
            // split 1: lo x hi
            #pragma unroll
            for (int nt = 0; nt < 8; nt++)
                #pragma unroll
                for (int mt = 0; mt < 4; mt++)
                    mma16n8k8(acc[mt][nt], al[mt][0], al[mt][1], al[mt][2], al[mt][3],
                              bh[nt][0], bh[nt][1]);
            // split 2: hi x lo
            #pragma unroll
            for (int nt = 0; nt < 8; nt++) {
                int rb = (warpN * 64 + nt * 8 + qrow) * RS + kk + qcol;
                uint32_t bl0 = Bl[rb], bl1 = Bl[rb + 4];
                #pragma unroll
                for (int mt = 0; mt < 4; mt++)
                    mma16n8k8(acc[mt][nt], ah[mt][0], ah[mt][1], ah[mt][2], ah[mt][3],
                              bl0, bl1);
            }
        }

        if ((g & 7) == 7) {       // chunk complete: fold into running argmin
            const int chunk = g >> 3;
            #pragma unroll
            for (int nt = 0; nt < 8; nt++) {
                int col0 = chunk * NCHUNK + warpN * 64 + nt * 8 + 2 * qcol;
                float e0 = g_embsq[col0];
                float e1 = g_embsq[col0 + 1];
                #pragma unroll
                for (int mt = 0; mt < 4; mt++) {
                    float d0 = fmaf(-2.f, acc[mt][nt][0], e0);
                    float d1 = fmaf(-2.f, acc[mt][nt][1], e1);
                    float d2 = fmaf(-2.f, acc[mt][nt][2], e0);
                    float d3 = fmaf(-2.f, acc[mt][nt][3], e1);
                    int s0 = mt * 2, s1 = mt * 2 + 1;
                    if (d0 < minv[s0]) { minv[s0] = d0; mini[s0] = col0; }
                    if (d1 < minv[s0]) { minv[s0] = d1; mini[s0] = col0 + 1; }
                    if (d2 < minv[s1]) { minv[s1] = d2; mini[s1] = col0; }
                    if (d3 < minv[s1]) { minv[s1] = d3; mini[s1] = col0 + 1; }
                    acc[mt][nt][0] = 0.f; acc[mt][nt][1] = 0.f;
                    acc[mt][nt][2] = 0.f; acc[mt][nt][3] = 0.f;
                }
            }
        }
        __syncthreads();
    }

    // reduce: quad (lanes sharing a row) then across warpN via smem
    #pragma unroll
    for (int mt = 0; mt < 4; mt++)
        #pragma unroll
        for (int h = 0; h < 2; h++) {
            int s = mt * 2 + h;
            float v = minv[s];
            int   idx = mini[s];
            #pragma unroll
            for (int off = 1; off <= 2; off <<= 1) {
                float ov = __shfl_xor_sync(0xffffffffu, v, off);
                int   oi = __shfl_xor_sync(0xffffffffu, idx, off);
                if (ov < v || (ov == v && oi < idx)) { v = ov; idx = oi; }
            }
            if (qcol == 0) {
                int row = warpM * 64 + mt * 16 + h * 8 + qrow;
                s_minv[row][warpN] = v;
                s_mini[row][warpN] = idx;
            }
        }
    __syncthreads();
    if (tid < 128) {
        float bv = s_minv[tid][0];
        int   bi = s_mini[tid][0];
        #pragma unroll
        for (int n = 1; n < 4; n++) {
            float v = s_minv[tid][n];
            int   i = s_mini[tid][n];
            if (v < bv || (v == bv && i < bi)) { bv = v; bi = i; }
        }
        g_idx[rowBase + tid] = bi;
    }
}

// ---------------- kernel 3: gather quantized, loss, scatter EMA stats ----------------
__global__ void gather_kernel(const float* __restrict__ x, float* __restrict__ out) {
    int row = blockIdx.x;
    int d = threadIdx.x;
    int idx = g_idx[row];
    float xv = x[(long)row * DDIM + d];
    float qv = g_emb[(long)idx * DDIM + d];
    out[OFF_Q + (long)row * DDIM + d] = qv;

    float diff = qv - xv;
    float s = diff * diff;
    #pragma unroll
    for (int off = 16; off; off >>= 1) s += __shfl_down_sync(0xffffffffu, s, off);
    __shared__ float ws[8];
    if ((d & 31) == 0) ws[d >> 5] = s;
    __syncthreads();
    if (d == 0) {
        float t = 0.f;
        #pragma unroll
        for (int i = 0; i < 8; i++) t += ws[i];
        atomicAdd(&g_loss, t);
        atomicAdd(&g_counts[idx], 1.0f);
        out[OFF_IDX + row] = (float)idx;
    }
    atomicAdd(&g_dw[(long)idx * DDIM + d], xv);
}

// ---------------- kernel 4a: new_cluster_size + sum n ----------------
__global__ void cs_kernel(const float* __restrict__ cluster_size, float* __restrict__ out) {
    int k = blockIdx.x * 256 + threadIdx.x;
    float ncs = cluster_size[k] * DECAY + ONE_M_DECAY * g_counts[k];
    out[OFF_CS + k] = ncs;
    float s = ncs;
    #pragma unroll
    for (int off = 16; off; off >>= 1) s += __shfl_down_sync(0xffffffffu, s, off);
    __shared__ float ws[8];
    if ((threadIdx.x & 31) == 0) ws[threadIdx.x >> 5] = s;
    __syncthreads();
    if (threadIdx.x == 0) {
        float t = 0.f;
        #pragma unroll
        for (int i = 0; i < 8; i++) t += ws[i];
        atomicAdd(&g_nsum, t);
    }
}

// ---------------- kernel 4b: new_ema_w ----------------
__global__ void emaw_kernel(const float* __restrict__ ema_w, float* __restrict__ out) {
    long i = (long)blockIdx.x * blockDim.x + threadIdx.x;
    if (i < (long)KCODES * DDIM)
        out[OFF_EMAW + i] = ema_w[i] * DECAY + ONE_M_DECAY * g_dw[i];
}

// ---------------- kernel 5: smoothed normalize + loss write ----------------
__global__ void final_kernel(float* __restrict__ out) {
    int k = blockIdx.x;
    int d = threadIdx.x;
    float n = g_nsum;
    float ncs = out[OFF_CS + k];
    float smoothed = (ncs + EPSV) / (n + (float)KCODES * EPSV) * n;
    out[OFF_EMB + (long)k * DDIM + d] = out[OFF_EMAW + (long)k * DDIM + d] / smoothed;
    if (k == 0 && d == 0)
        out[OFF_LOSS] = 2.0f * g_loss / (float)((long)NROWS * DDIM);
}

// ---------------- launch ----------------
extern "C" void kernel_launch(void* const* d_in, const int* in_sizes, int n_in,
                              void* d_out, int out_size) {
    const float* x         = (const float*)d_in[0];
    const float* embedding = (const float*)d_in[1];
    const float* amean     = (const float*)d_in[2];
    const float* astd      = (const float*)d_in[3];
    const float* cs        = (const float*)d_in[4];
    const float* ema_w     = (const float*)d_in[5];
    float* out = (float*)d_out;

    (void)in_sizes; (void)n_in; (void)out_size;

    cudaFuncSetAttribute(argmin_kernel, cudaFuncAttributeMaxDynamicSharedMemorySize,
                         2 * BUF_F * 4);

    zero_kernel<<<2048, 256>>>();
    xsplit_kernel<<<NROWS * DDIM / 256, 256>>>(x);
    prep_kernel<<<KCODES, 256>>>(embedding, amean, astd);
    argmin_kernel<<<NROWS / 128, 256, 2 * BUF_F * 4>>>();
    gather_kernel<<<NROWS, 256>>>(x, out);
    cs_kernel<<<KCODES / 256, 256>>>(cs, out);
    emaw_kernel<<<(KCODES * DDIM + 255) / 256, 256>>>(ema_w, out);
    final_kernel<<<KCODES, 256>>>(out);
}